// round 1
// baseline (speedup 1.0000x reference)
#include <cuda_runtime.h>
#include <math_constants.h>

#define S_LEN   2048
#define DHEAD   64
#define BM      64
#define BN      64
#define NTILES  (S_LEN / BN)
#define NTHREADS 128
#define KSTRIDE 68   // padded stride for transposed K tile (16B aligned, kills store conflicts)

// Shared memory layout (floats):
//   Qs  [64][64]      row-major query tile
//   Kst [64][68]      k-major (transposed) key tile: Kst[k][n]
//   Vs  [64][64]      row-major value tile
//   Ps  [64][64]      probabilities tile
#define SMEM_FLOATS (BM*DHEAD + DHEAD*KSTRIDE + BN*DHEAD + BM*BN)
#define SMEM_BYTES  (SMEM_FLOATS * 4)

__global__ void __launch_bounds__(NTHREADS)
fattn_fp32_kernel(const float* __restrict__ Qg,
                  const float* __restrict__ Kg,
                  const float* __restrict__ Vg,
                  float* __restrict__ Og) {
    extern __shared__ float sm[];
    float* Qs  = sm;                       // 4096
    float* Kst = Qs + BM * DHEAD;          // 4352
    float* Vs  = Kst + DHEAD * KSTRIDE;    // 4096
    float* Ps  = Vs + BN * DHEAD;          // 4096

    const int tid = threadIdx.x;
    const int tx = tid & 7;        // column group (8 groups of 8 cols)
    const int ty = tid >> 3;       // row group    (16 groups of 4 rows)
    const size_t base = (size_t)blockIdx.y * ((size_t)S_LEN * DHEAD);
    const int q0 = blockIdx.x * BM;

    // ---- load Q tile (row-major, coalesced float4) ----
    {
        const int r0 = tid >> 4;          // 0..7
        const int c4 = (tid & 15) * 4;    // 0..60
        const float* src = Qg + base + (size_t)q0 * DHEAD;
        #pragma unroll
        for (int it = 0; it < 8; ++it) {
            int m = r0 + it * 8;
            *(float4*)&Qs[m * DHEAD + c4] = *(const float4*)&src[m * DHEAD + c4];
        }
    }

    float o[4][8];
    #pragma unroll
    for (int i = 0; i < 4; ++i)
        #pragma unroll
        for (int j = 0; j < 8; ++j) o[i][j] = 0.f;

    float mrow[4], lrow[4];
    #pragma unroll
    for (int i = 0; i < 4; ++i) { mrow[i] = -CUDART_INF_F; lrow[i] = 0.f; }

    const float sc = 0.125f;   // 1/sqrt(64)

    for (int t = 0; t < NTILES; ++t) {
        __syncthreads();   // previous tile's P@V fully done before overwriting K/V

        // ---- load K tile transposed: Kst[k][n] ----
        // lane mapping n = tid&7 keeps scalar STS at only 2-way bank conflict
        {
            const int n0 = tid & 7;
            const int kq = (tid >> 3) * 4;   // 0,4,...,60
            const float* src = Kg + base + (size_t)t * (BN * DHEAD);
            #pragma unroll
            for (int r = 0; r < 8; ++r) {
                int n = n0 + r * 8;
                float4 kv = *(const float4*)&src[n * DHEAD + kq];
                Kst[(kq + 0) * KSTRIDE + n] = kv.x;
                Kst[(kq + 1) * KSTRIDE + n] = kv.y;
                Kst[(kq + 2) * KSTRIDE + n] = kv.z;
                Kst[(kq + 3) * KSTRIDE + n] = kv.w;
            }
        }
        // ---- load V tile row-major ----
        {
            const int r0 = tid >> 4;
            const int c4 = (tid & 15) * 4;
            const float* src = Vg + base + (size_t)t * (BN * DHEAD);
            #pragma unroll
            for (int it = 0; it < 8; ++it) {
                int n = r0 + it * 8;
                *(float4*)&Vs[n * DHEAD + c4] = *(const float4*)&src[n * DHEAD + c4];
            }
        }
        __syncthreads();

        // ---- S = Q @ K^T : 4x8 register tile per thread ----
        float acc[4][8];
        #pragma unroll
        for (int i = 0; i < 4; ++i)
            #pragma unroll
            for (int j = 0; j < 8; ++j) acc[i][j] = 0.f;

        #pragma unroll 2
        for (int k4 = 0; k4 < 16; ++k4) {
            float4 a4[4];
            #pragma unroll
            for (int i = 0; i < 4; ++i)
                a4[i] = *(const float4*)&Qs[(ty * 4 + i) * DHEAD + k4 * 4];
            #pragma unroll
            for (int kk = 0; kk < 4; ++kk) {
                const float* krow = &Kst[(k4 * 4 + kk) * KSTRIDE + tx * 8];
                float4 b0 = *(const float4*)krow;
                float4 b1 = *(const float4*)(krow + 4);
                float bb[8] = {b0.x, b0.y, b0.z, b0.w, b1.x, b1.y, b1.z, b1.w};
                #pragma unroll
                for (int i = 0; i < 4; ++i) {
                    float av = ((const float*)&a4[i])[kk];
                    #pragma unroll
                    for (int j = 0; j < 8; ++j)
                        acc[i][j] = fmaf(av, bb[j], acc[i][j]);
                }
            }
        }

        // ---- online softmax (rows live within an 8-lane group) ----
        #pragma unroll
        for (int i = 0; i < 4; ++i) {
            float mx = acc[i][0];
            #pragma unroll
            for (int j = 1; j < 8; ++j) mx = fmaxf(mx, acc[i][j]);
            mx = fmaxf(mx, __shfl_xor_sync(0xffffffffu, mx, 1));
            mx = fmaxf(mx, __shfl_xor_sync(0xffffffffu, mx, 2));
            mx = fmaxf(mx, __shfl_xor_sync(0xffffffffu, mx, 4));
            mx *= sc;
            float mnew = fmaxf(mrow[i], mx);
            float corr = __expf(mrow[i] - mnew);   // 0 on first tile (-inf)
            mrow[i] = mnew;

            float p[8];
            float rs = 0.f;
            #pragma unroll
            for (int j = 0; j < 8; ++j) {
                p[j] = __expf(fmaf(acc[i][j], sc, -mnew));
                rs += p[j];
            }
            rs += __shfl_xor_sync(0xffffffffu, rs, 1);
            rs += __shfl_xor_sync(0xffffffffu, rs, 2);
            rs += __shfl_xor_sync(0xffffffffu, rs, 4);
            lrow[i] = lrow[i] * corr + rs;
            #pragma unroll
            for (int j = 0; j < 8; ++j) o[i][j] *= corr;

            *(float4*)&Ps[(ty * 4 + i) * BN + tx * 8]     = make_float4(p[0], p[1], p[2], p[3]);
            *(float4*)&Ps[(ty * 4 + i) * BN + tx * 8 + 4] = make_float4(p[4], p[5], p[6], p[7]);
        }
        // each thread re-reads only rows its own warp wrote -> warp sync suffices
        __syncwarp();

        // ---- O += P @ V ----
        #pragma unroll 2
        for (int n4 = 0; n4 < 16; ++n4) {
            float4 p4[4];
            #pragma unroll
            for (int i = 0; i < 4; ++i)
                p4[i] = *(const float4*)&Ps[(ty * 4 + i) * BN + n4 * 4];
            #pragma unroll
            for (int nn = 0; nn < 4; ++nn) {
                const float* vrow = &Vs[(n4 * 4 + nn) * DHEAD + tx * 8];
                float4 v0 = *(const float4*)vrow;
                float4 v1 = *(const float4*)(vrow + 4);
                float vv[8] = {v0.x, v0.y, v0.z, v0.w, v1.x, v1.y, v1.z, v1.w};
                #pragma unroll
                for (int i = 0; i < 4; ++i) {
                    float pv = ((const float*)&p4[i])[nn];
                    #pragma unroll
                    for (int j = 0; j < 8; ++j)
                        o[i][j] = fmaf(pv, vv[j], o[i][j]);
                }
            }
        }
    }

    // ---- epilogue: normalize and store ----
    #pragma unroll
    for (int i = 0; i < 4; ++i) {
        float inv = 1.f / lrow[i];
        int m = q0 + ty * 4 + i;
        float* dst = Og + base + (size_t)m * DHEAD + tx * 8;
        *(float4*)dst       = make_float4(o[i][0] * inv, o[i][1] * inv, o[i][2] * inv, o[i][3] * inv);
        *(float4*)(dst + 4) = make_float4(o[i][4] * inv, o[i][5] * inv, o[i][6] * inv, o[i][7] * inv);
    }
}

extern "C" void kernel_launch(void* const* d_in, const int* in_sizes, int n_in,
                              void* d_out, int out_size) {
    const float* Q = (const float*)d_in[0];
    const float* K = (const float*)d_in[1];
    const float* V = (const float*)d_in[2];
    float* O = (float*)d_out;
    (void)in_sizes; (void)n_in; (void)out_size;

    cudaFuncSetAttribute(fattn_fp32_kernel,
                         cudaFuncAttributeMaxDynamicSharedMemorySize, SMEM_BYTES);

    dim3 grid(S_LEN / BM, 4 * 16);   // 32 query blocks x (B*H)=64
    fattn_fp32_kernel<<<grid, NTHREADS, SMEM_BYTES>>>(Q, K, V, O);
}

// round 2
// speedup vs baseline: 5.5470x; 5.5470x over previous
#include <cuda_runtime.h>
#include <math_constants.h>

#define S_LEN   2048
#define DHEAD   64
#define BM      64
#define BN      64
#define NTILES  (S_LEN / BN)
#define NTHREADS 128
#define PAD     68

#define SMEM_BYTES ((BM*PAD + BN*PAD + BN*PAD) * 4)

__device__ __forceinline__ unsigned f2tf(float x) {
    unsigned u; asm("cvt.rna.tf32.f32 %0, %1;" : "=r"(u) : "f"(x)); return u;
}

__device__ __forceinline__ void mma8(float c[4],
                                     unsigned a0, unsigned a1, unsigned a2, unsigned a3,
                                     unsigned b0, unsigned b1) {
    asm volatile(
        "mma.sync.aligned.m16n8k8.row.col.f32.tf32.tf32.f32 "
        "{%0,%1,%2,%3}, {%4,%5,%6,%7}, {%8,%9}, {%0,%1,%2,%3};"
        : "+f"(c[0]), "+f"(c[1]), "+f"(c[2]), "+f"(c[3])
        : "r"(a0), "r"(a1), "r"(a2), "r"(a3), "r"(b0), "r"(b1));
}

__global__ void __launch_bounds__(NTHREADS)
fattn_tf32_kernel(const float* __restrict__ Qg, const float* __restrict__ Kg,
                  const float* __restrict__ Vg, float* __restrict__ Og) {
    extern __shared__ float sm[];
    float* Qs = sm;                 // [BM][PAD]
    float* Ks = Qs + BM * PAD;      // [BN][PAD]  (key-major: Ks[key][d])
    float* Vs = Ks + BN * PAD;      // [BN][PAD]  (key-major: Vs[key][d])

    const int tid  = threadIdx.x;
    const int wid  = tid >> 5;
    const int lane = tid & 31;
    const int g    = lane >> 2;     // group id (row within m16 tile)
    const int q    = lane & 3;      // thread-in-group (quad col)
    const size_t base = (size_t)blockIdx.y * (size_t)(S_LEN * DHEAD);
    const int q0 = blockIdx.x * BM;

    // ---- Q tile -> smem, rounded to tf32 ----
    {
        const int r0 = tid >> 4;
        const int c4 = (tid & 15) * 4;
        const float* src = Qg + base + (size_t)q0 * DHEAD;
        #pragma unroll
        for (int it = 0; it < 8; ++it) {
            int m = r0 + it * 8;
            float4 v = *(const float4*)&src[m * DHEAD + c4];
            float4 w;
            w.x = __uint_as_float(f2tf(v.x));
            w.y = __uint_as_float(f2tf(v.y));
            w.z = __uint_as_float(f2tf(v.z));
            w.w = __uint_as_float(f2tf(v.w));
            *(float4*)&Qs[m * PAD + c4] = w;
        }
    }
    __syncthreads();

    // ---- Q fragments: loaded ONCE, reused for all 32 key tiles ----
    unsigned qa[8][4];
    {
        const int r = wid * 16 + g;
        #pragma unroll
        for (int k = 0; k < 8; ++k) {
            qa[k][0] = __float_as_uint(Qs[r * PAD + k * 8 + q]);
            qa[k][1] = __float_as_uint(Qs[(r + 8) * PAD + k * 8 + q]);
            qa[k][2] = __float_as_uint(Qs[r * PAD + k * 8 + q + 4]);
            qa[k][3] = __float_as_uint(Qs[(r + 8) * PAD + k * 8 + q + 4]);
        }
    }

    float o[8][4];
    #pragma unroll
    for (int n = 0; n < 8; ++n)
        #pragma unroll
        for (int i = 0; i < 4; ++i) o[n][i] = 0.f;

    float m0 = -CUDART_INF_F, m1 = -CUDART_INF_F;
    float l0 = 0.f, l1 = 0.f;
    const float sc = 0.125f;   // 1/sqrt(64)

    for (int t = 0; t < NTILES; ++t) {
        __syncthreads();   // previous tile's MMA reads of Ks/Vs complete
        // ---- load K/V tile -> smem, rounded to tf32 ----
        {
            const int r0 = tid >> 4;
            const int c4 = (tid & 15) * 4;
            const float* ksrc = Kg + base + (size_t)(t * BN) * DHEAD;
            const float* vsrc = Vg + base + (size_t)(t * BN) * DHEAD;
            #pragma unroll
            for (int it = 0; it < 8; ++it) {
                int n = r0 + it * 8;
                float4 kv = *(const float4*)&ksrc[n * DHEAD + c4];
                float4 vv = *(const float4*)&vsrc[n * DHEAD + c4];
                float4 a, b;
                a.x = __uint_as_float(f2tf(kv.x));
                a.y = __uint_as_float(f2tf(kv.y));
                a.z = __uint_as_float(f2tf(kv.z));
                a.w = __uint_as_float(f2tf(kv.w));
                b.x = __uint_as_float(f2tf(vv.x));
                b.y = __uint_as_float(f2tf(vv.y));
                b.z = __uint_as_float(f2tf(vv.z));
                b.w = __uint_as_float(f2tf(vv.w));
                *(float4*)&Ks[n * PAD + c4] = a;
                *(float4*)&Vs[n * PAD + c4] = b;
            }
        }
        __syncthreads();

        // ---- S = Q @ K^T (tensor cores) ----
        float s[8][4];
        #pragma unroll
        for (int n = 0; n < 8; ++n)
            #pragma unroll
            for (int i = 0; i < 4; ++i) s[n][i] = 0.f;

        #pragma unroll
        for (int n = 0; n < 8; ++n) {
            const float* kb = &Ks[(n * 8 + g) * PAD + q];
            #pragma unroll
            for (int k = 0; k < 8; ++k) {
                unsigned b0 = __float_as_uint(kb[k * 8]);
                unsigned b1 = __float_as_uint(kb[k * 8 + 4]);
                mma8(s[n], qa[k][0], qa[k][1], qa[k][2], qa[k][3], b0, b1);
            }
        }

        // ---- online softmax, fully in registers ----
        // rows: r0 = wid*16+g (regs 0,1), r1 = r0+8 (regs 2,3); quad lanes share a row
        float mx0 = s[0][0], mx1 = s[0][2];
        #pragma unroll
        for (int n = 0; n < 8; ++n) {
            mx0 = fmaxf(mx0, fmaxf(s[n][0], s[n][1]));
            mx1 = fmaxf(mx1, fmaxf(s[n][2], s[n][3]));
        }
        mx0 = fmaxf(mx0, __shfl_xor_sync(0xffffffffu, mx0, 1));
        mx0 = fmaxf(mx0, __shfl_xor_sync(0xffffffffu, mx0, 2));
        mx1 = fmaxf(mx1, __shfl_xor_sync(0xffffffffu, mx1, 1));
        mx1 = fmaxf(mx1, __shfl_xor_sync(0xffffffffu, mx1, 2));

        float n0 = fmaxf(m0, mx0 * sc);
        float n1 = fmaxf(m1, mx1 * sc);
        float c0 = __expf(m0 - n0);   // first tile: exp(-inf) = 0
        float c1 = __expf(m1 - n1);
        m0 = n0; m1 = n1;

        float a0 = 0.f, a1 = 0.f;
        #pragma unroll
        for (int n = 0; n < 8; ++n) {
            float p0 = __expf(fmaf(s[n][0], sc, -n0));
            float p1 = __expf(fmaf(s[n][1], sc, -n0));
            float p2 = __expf(fmaf(s[n][2], sc, -n1));
            float p3 = __expf(fmaf(s[n][3], sc, -n1));
            a0 += p0 + p1;
            a1 += p2 + p3;
            // round P to tf32 in-place (C-fragment reused as A-fragment below)
            s[n][0] = __uint_as_float(f2tf(p0));
            s[n][1] = __uint_as_float(f2tf(p1));
            s[n][2] = __uint_as_float(f2tf(p2));
            s[n][3] = __uint_as_float(f2tf(p3));
        }
        a0 += __shfl_xor_sync(0xffffffffu, a0, 1);
        a0 += __shfl_xor_sync(0xffffffffu, a0, 2);
        a1 += __shfl_xor_sync(0xffffffffu, a1, 1);
        a1 += __shfl_xor_sync(0xffffffffu, a1, 2);
        l0 = l0 * c0 + a0;
        l1 = l1 * c1 + a1;

        #pragma unroll
        for (int n = 0; n < 8; ++n) {
            o[n][0] *= c0; o[n][1] *= c0;
            o[n][2] *= c1; o[n][3] *= c1;
        }

        // ---- O += P @ V (tensor cores) ----
        // P stays in C-fragment layout; operand order {c0,c2,c1,c3} maps it to the
        // A-fragment with column permutation sigma = [0,2,4,6,1,3,5,7]; V B-fragment
        // rows are loaded pre-permuted (rows 2q and 2q+1) to compensate.
        #pragma unroll
        for (int k = 0; k < 8; ++k) {
            const float* vb0 = &Vs[(k * 8 + 2 * q) * PAD + g];
            const float* vb1 = &Vs[(k * 8 + 2 * q + 1) * PAD + g];
            unsigned pa0 = __float_as_uint(s[k][0]);
            unsigned pa1 = __float_as_uint(s[k][2]);
            unsigned pa2 = __float_as_uint(s[k][1]);
            unsigned pa3 = __float_as_uint(s[k][3]);
            #pragma unroll
            for (int n = 0; n < 8; ++n) {
                unsigned b0 = __float_as_uint(vb0[n * 8]);
                unsigned b1 = __float_as_uint(vb1[n * 8]);
                mma8(o[n], pa0, pa1, pa2, pa3, b0, b1);
            }
        }
    }

    // ---- epilogue: normalize + store ----
    const float i0 = 1.f / l0;
    const float i1 = 1.f / l1;
    const int r = q0 + wid * 16 + g;
    #pragma unroll
    for (int n = 0; n < 8; ++n) {
        int c = n * 8 + 2 * q;
        float2 u0 = make_float2(o[n][0] * i0, o[n][1] * i0);
        float2 u1 = make_float2(o[n][2] * i1, o[n][3] * i1);
        *(float2*)&Og[base + (size_t)r * DHEAD + c] = u0;
        *(float2*)&Og[base + (size_t)(r + 8) * DHEAD + c] = u1;
    }
}

extern "C" void kernel_launch(void* const* d_in, const int* in_sizes, int n_in,
                              void* d_out, int out_size) {
    const float* Q = (const float*)d_in[0];
    const float* K = (const float*)d_in[1];
    const float* V = (const float*)d_in[2];
    float* O = (float*)d_out;
    (void)in_sizes; (void)n_in; (void)out_size;

    cudaFuncSetAttribute(fattn_tf32_kernel,
                         cudaFuncAttributeMaxDynamicSharedMemorySize, SMEM_BYTES);

    dim3 grid(S_LEN / BM, 4 * 16);   // 32 q-blocks x (B*H)=64
    fattn_tf32_kernel<<<grid, NTHREADS, SMEM_BYTES>>>(Q, K, V, O);
}